// round 16
// baseline (speedup 1.0000x reference)
#include <cuda_runtime.h>
#include <cstdint>

// result = sum_j W[j] * S_j / T_j
//   T_j = sum_n y_true[n][j],  S_j = sum_n |y_true[n][j] - y_preds[n][j]|
//
// R7 hybrid (best 27.1us, 6.19 TB/s): 50% via 4-stage cp.async.bulk (TMA)
// pipeline, 50% via per-iteration inline LDG.128. ONLY change vs R7: the
// bulk copies carry an L2::evict_first cache-hint so the zero-reuse TMA
// stream doesn't compete with the LDG stream for L2 allocation.

__device__ float g_T[5] = {0.f, 0.f, 0.f, 0.f, 0.f};
__device__ float g_S[5] = {0.f, 0.f, 0.f, 0.f, 0.f};
__device__ unsigned int g_count = 0;

__constant__ float c_W[5] = {0.3f, 0.175f, 0.175f, 0.175f, 0.175f};

#define NSTAGES      4
#define CHUNK_FLOATS 2560                  // 640 threads * 4 floats; % 5 == 0
#define CHUNK_BYTES  (CHUNK_FLOATS * 4)    // 10240
#define STAGE_BYTES  (2 * CHUNK_BYTES)     // 20480 (yt chunk + yp chunk)
#define SMEM_BYTES   (NSTAGES * STAGE_BYTES)  // 81920 -> 2 blocks/SM
#define NBLOCKS      296
#define NTHREADS     640
#define TOT_THREADS  (NBLOCKS * NTHREADS)  // 189440, % 5 == 0

static __device__ __forceinline__ uint32_t s2u(const void* p) {
    return (uint32_t)__cvta_generic_to_shared(p);
}

static __device__ __forceinline__ void mbar_init(uint32_t mbar, uint32_t count) {
    asm volatile("mbarrier.init.shared.b64 [%0], %1;" :: "r"(mbar), "r"(count) : "memory");
}

static __device__ __forceinline__ void mbar_wait(uint32_t mbar, uint32_t phase) {
    uint32_t done;
    asm volatile(
        "{\n\t.reg .pred p;\n\t"
        "mbarrier.try_wait.parity.acquire.cta.shared::cta.b64 p, [%1], %2;\n\t"
        "selp.b32 %0, 1, 0, p;\n\t}"
        : "=r"(done) : "r"(mbar), "r"(phase) : "memory");
    while (!done) {
        asm volatile(
            "{\n\t.reg .pred p;\n\t"
            "mbarrier.try_wait.parity.acquire.cta.shared::cta.b64 p, [%1], %2, 0x989680;\n\t"
            "selp.b32 %0, 1, 0, p;\n\t}"
            : "=r"(done) : "r"(mbar), "r"(phase) : "memory");
    }
}

static __device__ __forceinline__ void issue_chunk(
    const char* __restrict__ yt, const char* __restrict__ yp,
    uint32_t stage_smem, uint32_t mbar, long long byte_off)
{
    asm volatile("mbarrier.arrive.expect_tx.shared.b64 _, [%0], %1;"
                 :: "r"(mbar), "r"((uint32_t)STAGE_BYTES) : "memory");
    // evict_first policy: TMA stream is zero-reuse, keep it out of L2's way.
    asm volatile(
        "{\n\t.reg .b64 pol;\n\t"
        "createpolicy.fractional.L2::evict_first.b64 pol, 1.0;\n\t"
        "cp.async.bulk.shared::cluster.global.mbarrier::complete_tx::bytes.L2::cache_hint"
        " [%0], [%1], %2, [%3], pol;\n\t"
        "cp.async.bulk.shared::cluster.global.mbarrier::complete_tx::bytes.L2::cache_hint"
        " [%4], [%5], %6, [%3], pol;\n\t}"
        :: "r"(stage_smem), "l"(yt + byte_off), "r"((uint32_t)CHUNK_BYTES), "r"(mbar),
           "r"(stage_smem + CHUNK_BYTES), "l"(yp + byte_off), "r"((uint32_t)CHUNK_BYTES)
        : "memory");
}

// Rotate 4 slot-accumulators (slot k holds column (c0+k)%5) into absolute cols.
#define ROT_CASE(C)                                                           \
    case C:                                                                   \
        cT[(C+0)%5]=AT[0]; cT[(C+1)%5]=AT[1]; cT[(C+2)%5]=AT[2];              \
        cT[(C+3)%5]=AT[3]; cT[(C+4)%5]=0.f;                                   \
        cS[(C+0)%5]=AS[0]; cS[(C+1)%5]=AS[1]; cS[(C+2)%5]=AS[2];              \
        cS[(C+3)%5]=AS[3]; cS[(C+4)%5]=0.f;                                   \
        break;

__global__ void __launch_bounds__(NTHREADS, 2) fused_loss_hybrid_kernel(
    const char* __restrict__ yt,
    const char* __restrict__ yp,
    int n_floats,
    float* __restrict__ out)
{
    extern __shared__ char dynbuf[];
    __shared__ unsigned long long full_bar[NSTAGES];
    __shared__ float sT[5];
    __shared__ float sS[5];
    __shared__ bool is_last;

    const int tid  = threadIdx.x;
    const int bid  = blockIdx.x;
    const int gtid = bid * NTHREADS + tid;

    // --- split: TMA covers [0, n_tma), LDG covers [n_tma, n) ---
    // CHUNK_FLOATS % 20 == 0 -> n_tma is 0 mod 4 and mod 5.
    const int nchunks = (n_floats / 2) / CHUNK_FLOATS;      // 4096 for real input
    const int n_tma   = nchunks * CHUNK_FLOATS;

    const int cnt = (nchunks > bid) ? (nchunks - bid + NBLOCKS - 1) / NBLOCKS : 0;

    const int ldg_start4 = n_tma / 4;
    const int ldg_end4   = n_floats / 4;
    const int span4      = ldg_end4 - ldg_start4 - gtid;    // my float4 slots
    const int lcnt = (span4 > 0) ? (span4 + TOT_THREADS - 1) / TOT_THREADS : 0;

    const int L = (cnt > lcnt) ? cnt : lcnt;

    if (tid == 0) {
        #pragma unroll
        for (int s = 0; s < NSTAGES; s++) mbar_init(s2u(&full_bar[s]), 1);
    }
    if (tid < 5) { sT[tid] = 0.f; sS[tid] = 0.f; }
    __syncthreads();

    // Prologue: fill the TMA pipeline.
    if (tid == 0) {
        const int pro = (cnt < NSTAGES) ? cnt : NSTAGES;
        for (int l = 0; l < pro; l++) {
            const long long c = (long long)bid + (long long)l * NBLOCKS;
            issue_chunk(yt, yp, s2u(dynbuf) + l * STAGE_BYTES, s2u(&full_bar[l]),
                        c * (long long)CHUNK_BYTES);
        }
    }

    // Shared slot accumulators: both the TMA chunk phase (4*tid mod 5; chunk
    // start == 0 mod 5) and the LDG phase (4*gtid mod 5; NTHREADS,n_tma,stride
    // all == 0 mod 5) equal c0 = (4*tid) % 5 -> slots are column-consistent.
    float AT[4] = {0.f, 0.f, 0.f, 0.f};
    float AS[4] = {0.f, 0.f, 0.f, 0.f};

    const float4* yt4 = (const float4*)yt;
    const float4* yp4 = (const float4*)yp;
    int i4 = ldg_start4 + gtid;

    for (int l = 0; l < L; l++) {
        // ---- issue LDG pair first so it overlaps the mbarrier wait ----
        float4 lt, lp;
        const bool dl = (l < lcnt);
        if (dl) {
            lt = __ldcs(yt4 + i4);
            lp = __ldcs(yp4 + i4);
            i4 += TOT_THREADS;
        }

        if (l < cnt) {
            const int s  = l & (NSTAGES - 1);
            const int ph = (l >> 2) & 1;
            mbar_wait(s2u(&full_bar[s]), ph);

            const float4 t = ((const float4*)(dynbuf + s * STAGE_BYTES))[tid];
            const float4 p = ((const float4*)(dynbuf + s * STAGE_BYTES + CHUNK_BYTES))[tid];
            AT[0] += t.x; AS[0] += fabsf(t.x - p.x);
            AT[1] += t.y; AS[1] += fabsf(t.y - p.y);
            AT[2] += t.z; AS[2] += fabsf(t.z - p.z);
            AT[3] += t.w; AS[3] += fabsf(t.w - p.w);
        }

        if (dl) {
            AT[0] += lt.x; AS[0] += fabsf(lt.x - lp.x);
            AT[1] += lt.y; AS[1] += fabsf(lt.y - lp.y);
            AT[2] += lt.z; AS[2] += fabsf(lt.z - lp.z);
            AT[3] += lt.w; AS[3] += fabsf(lt.w - lp.w);
        }

        if (l < cnt) {                 // cnt is block-uniform -> sync is uniform
            __syncthreads();           // whole block done with stage s
            if (tid == 0 && l + NSTAGES < cnt) {
                const int s = l & (NSTAGES - 1);
                const long long c = (long long)bid + (long long)(l + NSTAGES) * NBLOCKS;
                issue_chunk(yt, yp, s2u(dynbuf) + s * STAGE_BYTES, s2u(&full_bar[s]),
                            c * (long long)CHUNK_BYTES);
            }
        }
    }

    // Rotate to absolute columns.
    float cT[5], cS[5];
    const int c0 = (tid * 4) % 5;
    switch (c0) {
        ROT_CASE(0) ROT_CASE(1) ROT_CASE(2) ROT_CASE(3) ROT_CASE(4)
        default: break;
    }

    // Warp butterfly reduction.
    #pragma unroll
    for (int off = 16; off > 0; off >>= 1) {
        #pragma unroll
        for (int j = 0; j < 5; j++) {
            cT[j] += __shfl_xor_sync(0xffffffffu, cT[j], off);
            cS[j] += __shfl_xor_sync(0xffffffffu, cS[j], off);
        }
    }
    if ((tid & 31) == 0) {
        #pragma unroll
        for (int j = 0; j < 5; j++) {
            atomicAdd(&sT[j], cT[j]);
            atomicAdd(&sS[j], cS[j]);
        }
    }
    __syncthreads();

    // Scalar leftover (none for the real input; correctness guard).
    const int rem_start = (n_floats / 4) * 4;
    if (bid == 0 && tid == 0 && rem_start < n_floats) {
        const float* ytf = (const float*)yt;
        const float* ypf = (const float*)yp;
        for (int idx = rem_start; idx < n_floats; idx++) {
            const int c = idx % 5;
            atomicAdd(&g_T[c], ytf[idx]);
            atomicAdd(&g_S[c], fabsf(ytf[idx] - ypf[idx]));
        }
    }

    if (tid < 5) {
        atomicAdd(&g_T[tid], sT[tid]);
        atomicAdd(&g_S[tid], sS[tid]);
    }
    __threadfence();

    if (tid == 0) {
        const unsigned int c = atomicAdd(&g_count, 1u);
        is_last = (c == gridDim.x - 1);
    }
    __syncthreads();

    if (is_last && tid == 0) {
        float r = 0.f;
        #pragma unroll
        for (int j = 0; j < 5; j++) {
            const float T = atomicAdd(&g_T[j], 0.f);
            const float S = atomicAdd(&g_S[j], 0.f);
            r += c_W[j] * S / T;
        }
        out[0] = r;
        #pragma unroll
        for (int j = 0; j < 5; j++) { g_T[j] = 0.f; g_S[j] = 0.f; }
        g_count = 0u;
        __threadfence();
    }
}

extern "C" void kernel_launch(void* const* d_in, const int* in_sizes, int n_in,
                              void* d_out, int out_size) {
    const char* yt = (const char*)d_in[0];
    const char* yp = (const char*)d_in[1];
    float* out = (float*)d_out;
    const int n = in_sizes[0];   // 20971520 floats

    static bool attr_set = false;
    if (!attr_set) {
        cudaFuncSetAttribute(fused_loss_hybrid_kernel,
                             cudaFuncAttributeMaxDynamicSharedMemorySize, SMEM_BYTES);
        attr_set = true;
    }

    fused_loss_hybrid_kernel<<<NBLOCKS, NTHREADS, SMEM_BYTES>>>(yt, yp, n, out);
}

// round 17
// speedup vs baseline: 1.3101x; 1.3101x over previous
#include <cuda_runtime.h>
#include <cstdint>

// result = sum_j W[j] * S_j / T_j
//   T_j = sum_n y_true[n][j],  S_j = sum_n |y_true[n][j] - y_preds[n][j]|
//
// FINAL (R7 verbatim, best measured 27.1us = 6.19 TB/s effective, ~97% of
// the measured joint streaming cap): 50% of the data via a 4-stage
// cp.async.bulk (TMA) pipeline, 50% via per-iteration inline LDG.128, so
// both memory request engines run concurrently. All tested variants
// (split re-balance, register double-buffer, warp specialization,
// producer/consumer mbarriers, uniform chunk rounding, L2 evict hints)
// measured equal or worse.

__device__ float g_T[5] = {0.f, 0.f, 0.f, 0.f, 0.f};
__device__ float g_S[5] = {0.f, 0.f, 0.f, 0.f, 0.f};
__device__ unsigned int g_count = 0;

__constant__ float c_W[5] = {0.3f, 0.175f, 0.175f, 0.175f, 0.175f};

#define NSTAGES      4
#define CHUNK_FLOATS 2560                  // 640 threads * 4 floats; % 5 == 0
#define CHUNK_BYTES  (CHUNK_FLOATS * 4)    // 10240
#define STAGE_BYTES  (2 * CHUNK_BYTES)     // 20480 (yt chunk + yp chunk)
#define SMEM_BYTES   (NSTAGES * STAGE_BYTES)  // 81920 -> 2 blocks/SM
#define NBLOCKS      296
#define NTHREADS     640
#define TOT_THREADS  (NBLOCKS * NTHREADS)  // 189440, % 5 == 0

static __device__ __forceinline__ uint32_t s2u(const void* p) {
    return (uint32_t)__cvta_generic_to_shared(p);
}

static __device__ __forceinline__ void mbar_init(uint32_t mbar, uint32_t count) {
    asm volatile("mbarrier.init.shared.b64 [%0], %1;" :: "r"(mbar), "r"(count) : "memory");
}

static __device__ __forceinline__ void mbar_wait(uint32_t mbar, uint32_t phase) {
    uint32_t done;
    asm volatile(
        "{\n\t.reg .pred p;\n\t"
        "mbarrier.try_wait.parity.acquire.cta.shared::cta.b64 p, [%1], %2;\n\t"
        "selp.b32 %0, 1, 0, p;\n\t}"
        : "=r"(done) : "r"(mbar), "r"(phase) : "memory");
    while (!done) {
        asm volatile(
            "{\n\t.reg .pred p;\n\t"
            "mbarrier.try_wait.parity.acquire.cta.shared::cta.b64 p, [%1], %2, 0x989680;\n\t"
            "selp.b32 %0, 1, 0, p;\n\t}"
            : "=r"(done) : "r"(mbar), "r"(phase) : "memory");
    }
}

static __device__ __forceinline__ void issue_chunk(
    const char* __restrict__ yt, const char* __restrict__ yp,
    uint32_t stage_smem, uint32_t mbar, long long byte_off)
{
    asm volatile("mbarrier.arrive.expect_tx.shared.b64 _, [%0], %1;"
                 :: "r"(mbar), "r"((uint32_t)STAGE_BYTES) : "memory");
    asm volatile(
        "cp.async.bulk.shared::cluster.global.mbarrier::complete_tx::bytes [%0], [%1], %2, [%3];"
        :: "r"(stage_smem), "l"(yt + byte_off), "r"((uint32_t)CHUNK_BYTES), "r"(mbar) : "memory");
    asm volatile(
        "cp.async.bulk.shared::cluster.global.mbarrier::complete_tx::bytes [%0], [%1], %2, [%3];"
        :: "r"(stage_smem + CHUNK_BYTES), "l"(yp + byte_off), "r"((uint32_t)CHUNK_BYTES), "r"(mbar) : "memory");
}

// Rotate 4 slot-accumulators (slot k holds column (c0+k)%5) into absolute cols.
#define ROT_CASE(C)                                                           \
    case C:                                                                   \
        cT[(C+0)%5]=AT[0]; cT[(C+1)%5]=AT[1]; cT[(C+2)%5]=AT[2];              \
        cT[(C+3)%5]=AT[3]; cT[(C+4)%5]=0.f;                                   \
        cS[(C+0)%5]=AS[0]; cS[(C+1)%5]=AS[1]; cS[(C+2)%5]=AS[2];              \
        cS[(C+3)%5]=AS[3]; cS[(C+4)%5]=0.f;                                   \
        break;

__global__ void __launch_bounds__(NTHREADS, 2) fused_loss_hybrid_kernel(
    const char* __restrict__ yt,
    const char* __restrict__ yp,
    int n_floats,
    float* __restrict__ out)
{
    extern __shared__ char dynbuf[];
    __shared__ unsigned long long full_bar[NSTAGES];
    __shared__ float sT[5];
    __shared__ float sS[5];
    __shared__ bool is_last;

    const int tid  = threadIdx.x;
    const int bid  = blockIdx.x;
    const int gtid = bid * NTHREADS + tid;

    // --- split: TMA covers [0, n_tma), LDG covers [n_tma, n) ---
    // CHUNK_FLOATS % 20 == 0 -> n_tma is 0 mod 4 and mod 5.
    const int nchunks = (n_floats / 2) / CHUNK_FLOATS;      // 4096 for real input
    const int n_tma   = nchunks * CHUNK_FLOATS;

    const int cnt = (nchunks > bid) ? (nchunks - bid + NBLOCKS - 1) / NBLOCKS : 0;

    const int ldg_start4 = n_tma / 4;
    const int ldg_end4   = n_floats / 4;
    const int span4      = ldg_end4 - ldg_start4 - gtid;    // my float4 slots
    const int lcnt = (span4 > 0) ? (span4 + TOT_THREADS - 1) / TOT_THREADS : 0;

    const int L = (cnt > lcnt) ? cnt : lcnt;

    if (tid == 0) {
        #pragma unroll
        for (int s = 0; s < NSTAGES; s++) mbar_init(s2u(&full_bar[s]), 1);
    }
    if (tid < 5) { sT[tid] = 0.f; sS[tid] = 0.f; }
    __syncthreads();

    // Prologue: fill the TMA pipeline.
    if (tid == 0) {
        const int pro = (cnt < NSTAGES) ? cnt : NSTAGES;
        for (int l = 0; l < pro; l++) {
            const long long c = (long long)bid + (long long)l * NBLOCKS;
            issue_chunk(yt, yp, s2u(dynbuf) + l * STAGE_BYTES, s2u(&full_bar[l]),
                        c * (long long)CHUNK_BYTES);
        }
    }

    // Shared slot accumulators: both the TMA chunk phase (4*tid mod 5; chunk
    // start == 0 mod 5) and the LDG phase (4*gtid mod 5; NTHREADS,n_tma,stride
    // all == 0 mod 5) equal c0 = (4*tid) % 5 -> slots are column-consistent.
    float AT[4] = {0.f, 0.f, 0.f, 0.f};
    float AS[4] = {0.f, 0.f, 0.f, 0.f};

    const float4* yt4 = (const float4*)yt;
    const float4* yp4 = (const float4*)yp;
    int i4 = ldg_start4 + gtid;

    for (int l = 0; l < L; l++) {
        // ---- issue LDG pair first so it overlaps the mbarrier wait ----
        float4 lt, lp;
        const bool dl = (l < lcnt);
        if (dl) {
            lt = __ldcs(yt4 + i4);
            lp = __ldcs(yp4 + i4);
            i4 += TOT_THREADS;
        }

        if (l < cnt) {
            const int s  = l & (NSTAGES - 1);
            const int ph = (l >> 2) & 1;
            mbar_wait(s2u(&full_bar[s]), ph);

            const float4 t = ((const float4*)(dynbuf + s * STAGE_BYTES))[tid];
            const float4 p = ((const float4*)(dynbuf + s * STAGE_BYTES + CHUNK_BYTES))[tid];
            AT[0] += t.x; AS[0] += fabsf(t.x - p.x);
            AT[1] += t.y; AS[1] += fabsf(t.y - p.y);
            AT[2] += t.z; AS[2] += fabsf(t.z - p.z);
            AT[3] += t.w; AS[3] += fabsf(t.w - p.w);
        }

        if (dl) {
            AT[0] += lt.x; AS[0] += fabsf(lt.x - lp.x);
            AT[1] += lt.y; AS[1] += fabsf(lt.y - lp.y);
            AT[2] += lt.z; AS[2] += fabsf(lt.z - lp.z);
            AT[3] += lt.w; AS[3] += fabsf(lt.w - lp.w);
        }

        if (l < cnt) {                 // cnt is block-uniform -> sync is uniform
            __syncthreads();           // whole block done with stage s
            if (tid == 0 && l + NSTAGES < cnt) {
                const int s = l & (NSTAGES - 1);
                const long long c = (long long)bid + (long long)(l + NSTAGES) * NBLOCKS;
                issue_chunk(yt, yp, s2u(dynbuf) + s * STAGE_BYTES, s2u(&full_bar[s]),
                            c * (long long)CHUNK_BYTES);
            }
        }
    }

    // Rotate to absolute columns.
    float cT[5], cS[5];
    const int c0 = (tid * 4) % 5;
    switch (c0) {
        ROT_CASE(0) ROT_CASE(1) ROT_CASE(2) ROT_CASE(3) ROT_CASE(4)
        default: break;
    }

    // Warp butterfly reduction.
    #pragma unroll
    for (int off = 16; off > 0; off >>= 1) {
        #pragma unroll
        for (int j = 0; j < 5; j++) {
            cT[j] += __shfl_xor_sync(0xffffffffu, cT[j], off);
            cS[j] += __shfl_xor_sync(0xffffffffu, cS[j], off);
        }
    }
    if ((tid & 31) == 0) {
        #pragma unroll
        for (int j = 0; j < 5; j++) {
            atomicAdd(&sT[j], cT[j]);
            atomicAdd(&sS[j], cS[j]);
        }
    }
    __syncthreads();

    // Scalar leftover (none for the real input; correctness guard).
    const int rem_start = (n_floats / 4) * 4;
    if (bid == 0 && tid == 0 && rem_start < n_floats) {
        const float* ytf = (const float*)yt;
        const float* ypf = (const float*)yp;
        for (int idx = rem_start; idx < n_floats; idx++) {
            const int c = idx % 5;
            atomicAdd(&g_T[c], ytf[idx]);
            atomicAdd(&g_S[c], fabsf(ytf[idx] - ypf[idx]));
        }
    }

    if (tid < 5) {
        atomicAdd(&g_T[tid], sT[tid]);
        atomicAdd(&g_S[tid], sS[tid]);
    }
    __threadfence();

    if (tid == 0) {
        const unsigned int c = atomicAdd(&g_count, 1u);
        is_last = (c == gridDim.x - 1);
    }
    __syncthreads();

    if (is_last && tid == 0) {
        float r = 0.f;
        #pragma unroll
        for (int j = 0; j < 5; j++) {
            const float T = atomicAdd(&g_T[j], 0.f);
            const float S = atomicAdd(&g_S[j], 0.f);
            r += c_W[j] * S / T;
        }
        out[0] = r;
        #pragma unroll
        for (int j = 0; j < 5; j++) { g_T[j] = 0.f; g_S[j] = 0.f; }
        g_count = 0u;
        __threadfence();
    }
}

extern "C" void kernel_launch(void* const* d_in, const int* in_sizes, int n_in,
                              void* d_out, int out_size) {
    const char* yt = (const char*)d_in[0];
    const char* yp = (const char*)d_in[1];
    float* out = (float*)d_out;
    const int n = in_sizes[0];   // 20971520 floats

    static bool attr_set = false;
    if (!attr_set) {
        cudaFuncSetAttribute(fused_loss_hybrid_kernel,
                             cudaFuncAttributeMaxDynamicSharedMemorySize, SMEM_BYTES);
        attr_set = true;
    }

    fused_loss_hybrid_kernel<<<NBLOCKS, NTHREADS, SMEM_BYTES>>>(yt, yp, n, out);
}